// round 1
// baseline (speedup 1.0000x reference)
#include <cuda_runtime.h>
#include <math.h>

#define D 128
#define NMAX 50000
#define EMAX 800000
#define BM 64

// Scratch (device globals — no allocation allowed in kernel_launch)
__device__ float g_xw[(size_t)NMAX * D];   // x @ W
__device__ float g_p1[NMAX];               // x . w_pred[:128]
__device__ float g_p2[NMAX];               // x . w_pred[128:]
__device__ float g_deg[NMAX];              // weighted in-degree (init 1.0 for self loop)
__device__ float g_dis[NMAX];              // deg^{-1/2}
__device__ float g_ew[EMAX];               // sigmoid edge weights

// ---------------------------------------------------------------------------
// Kernel 1: per-node dot products with the two halves of w_pred; init deg=1.
// One warp per node, coalesced 512B row read.
// ---------------------------------------------------------------------------
__global__ void k_precompute(const float* __restrict__ x,
                             const float* __restrict__ wp, int n) {
    int warp = (blockIdx.x * blockDim.x + threadIdx.x) >> 5;
    int lane = threadIdx.x & 31;
    if (warp >= n) return;
    float4 xv = ((const float4*)(x + (size_t)warp * D))[lane];
    float4 w1 = ((const float4*)wp)[lane];
    float4 w2 = ((const float4*)(wp + D))[lane];
    float s1 = xv.x * w1.x + xv.y * w1.y + xv.z * w1.z + xv.w * w1.w;
    float s2 = xv.x * w2.x + xv.y * w2.y + xv.z * w2.z + xv.w * w2.w;
#pragma unroll
    for (int o = 16; o > 0; o >>= 1) {
        s1 += __shfl_xor_sync(0xffffffffu, s1, o);
        s2 += __shfl_xor_sync(0xffffffffu, s2, o);
    }
    if (lane == 0) {
        g_p1[warp] = s1;
        g_p2[warp] = s2;
        g_deg[warp] = 1.0f;  // self-loop weight
    }
}

// ---------------------------------------------------------------------------
// Kernel 2: edge weights (sigmoid) + weighted in-degree via atomics.
// ---------------------------------------------------------------------------
__global__ void k_edge(const int* __restrict__ src, const int* __restrict__ tgt,
                       const float* __restrict__ bp, int e) {
    int i = blockIdx.x * blockDim.x + threadIdx.x;
    if (i >= e) return;
    int s = src[i], t = tgt[i];
    float z = g_p1[s] + g_p2[t] + bp[0];
    float w = 1.0f / (1.0f + expf(-z));
    g_ew[i] = w;
    atomicAdd(&g_deg[t], w);
}

// ---------------------------------------------------------------------------
// Kernel 3: xw = x @ W. W (64KB) + 64-row X tile (32KB) in dynamic smem.
// 256 threads, each computes 8 rows x 4 cols (register tile).
// ---------------------------------------------------------------------------
__global__ void k_gemm(const float* __restrict__ x, const float* __restrict__ W,
                       int n) {
    extern __shared__ float sh[];
    float* Ws = sh;            // [k][j]  128*128
    float* Xs = sh + D * D;    // [r][k]  BM*128
    int tid = threadIdx.x;
    int row0 = blockIdx.x * BM;

    for (int i = tid; i < D * D / 4; i += 256)
        ((float4*)Ws)[i] = ((const float4*)W)[i];
    for (int i = tid; i < BM * D / 4; i += 256) {
        int r = i >> 5;
        int gr = row0 + r;
        float4 v = make_float4(0.f, 0.f, 0.f, 0.f);
        if (gr < n) v = ((const float4*)x)[(size_t)gr * 32 + (i & 31)];
        ((float4*)Xs)[i] = v;
    }
    __syncthreads();

    int tcol = tid & 31;   // col group: cols tcol*4 .. +3 (LDS.128, conflict-free)
    int trow = tid >> 5;   // row group: rows trow*8 .. +7 (broadcast loads)
    float acc[8][4];
#pragma unroll
    for (int i = 0; i < 8; i++)
#pragma unroll
        for (int j = 0; j < 4; j++) acc[i][j] = 0.f;

#pragma unroll 4
    for (int k = 0; k < D; k++) {
        float4 bv = *((const float4*)&Ws[k * D + tcol * 4]);
        float av[8];
#pragma unroll
        for (int i = 0; i < 8; i++) av[i] = Xs[(trow * 8 + i) * D + k];
#pragma unroll
        for (int i = 0; i < 8; i++) {
            acc[i][0] += av[i] * bv.x;
            acc[i][1] += av[i] * bv.y;
            acc[i][2] += av[i] * bv.z;
            acc[i][3] += av[i] * bv.w;
        }
    }

#pragma unroll
    for (int i = 0; i < 8; i++) {
        int gr = row0 + trow * 8 + i;
        if (gr < n)
            *((float4*)&g_xw[(size_t)gr * D + tcol * 4]) =
                make_float4(acc[i][0], acc[i][1], acc[i][2], acc[i][3]);
    }
}

// ---------------------------------------------------------------------------
// Kernel 4: dis = rsqrt(deg); out = b + dis^2 * xw  (self-loop term + bias,
// also initializes the poisoned output buffer). One thread per float4.
// ---------------------------------------------------------------------------
__global__ void k_selfinit(const float* __restrict__ b, float* __restrict__ out,
                           int n) {
    int i = blockIdx.x * blockDim.x + threadIdx.x;
    if (i >= n * 32) return;
    int node = i >> 5;
    int c4 = i & 31;
    float dg = g_deg[node];
    float ds = (dg > 0.f) ? rsqrtf(dg) : 0.f;
    float sc = ds * ds;
    float4 xv = ((const float4*)g_xw)[i];
    float4 bv = ((const float4*)b)[c4];
    ((float4*)out)[i] = make_float4(bv.x + sc * xv.x, bv.y + sc * xv.y,
                                    bv.z + sc * xv.z, bv.w + sc * xv.w);
    if (c4 == 0) g_dis[node] = ds;
}

// ---------------------------------------------------------------------------
// Kernel 5: edge scatter. Warp per edge: gather xw[src] (L2-resident),
// scale by dis[src]*ew*dis[tgt], RED.ADD.F32 into out[tgt].
// ---------------------------------------------------------------------------
__global__ void k_scatter(const int* __restrict__ src, const int* __restrict__ tgt,
                          float* __restrict__ out, int e) {
    int w = (blockIdx.x * blockDim.x + threadIdx.x) >> 5;
    int lane = threadIdx.x & 31;
    if (w >= e) return;
    int s = src[w], t = tgt[w];
    float c = g_dis[s] * g_ew[w] * g_dis[t];
    float4 v = ((const float4*)g_xw)[(size_t)s * 32 + lane];
    float* o = out + (size_t)t * D + lane * 4;
    atomicAdd(o + 0, c * v.x);
    atomicAdd(o + 1, c * v.y);
    atomicAdd(o + 2, c * v.z);
    atomicAdd(o + 3, c * v.w);
}

// ---------------------------------------------------------------------------
extern "C" void kernel_launch(void* const* d_in, const int* in_sizes, int n_in,
                              void* d_out, int out_size) {
    const float* x  = (const float*)d_in[0];
    const int*   ei = (const int*)d_in[1];
    const float* W  = (const float*)d_in[2];
    const float* b  = (const float*)d_in[3];
    const float* wp = (const float*)d_in[4];
    const float* bp = (const float*)d_in[5];
    float* out = (float*)d_out;

    int n = in_sizes[0] / D;
    int e = in_sizes[1] / 2;
    const int* src = ei;
    const int* tgt = ei + e;

    int smem = (D * D + BM * D) * (int)sizeof(float);  // 96 KB
    cudaFuncSetAttribute(k_gemm, cudaFuncAttributeMaxDynamicSharedMemorySize, smem);

    k_precompute<<<(n + 7) / 8, 256>>>(x, wp, n);
    k_edge<<<(e + 255) / 256, 256>>>(src, tgt, bp, e);
    k_gemm<<<(n + BM - 1) / BM, 256, smem>>>(x, W, n);
    k_selfinit<<<(n * 32 + 255) / 256, 256>>>(b, out, n);
    k_scatter<<<(e * 32 + 255) / 256, 256>>>(src, tgt, out, e);
}

// round 2
// speedup vs baseline: 1.7310x; 1.7310x over previous
#include <cuda_runtime.h>
#include <math.h>

#define D 128
#define NMAX 50000
#define EMAX 800000
#define BM 64

// Scratch (device globals — no allocation allowed in kernel_launch)
__device__ float g_xw[(size_t)NMAX * D];   // x @ W
__device__ float g_p1[NMAX];               // x . w_pred[:128]
__device__ float g_p2[NMAX];               // x . w_pred[128:]
__device__ float g_deg[NMAX];              // weighted in-degree (init 1.0 self loop)
__device__ float g_dis[NMAX];              // deg^{-1/2}
__device__ float g_ew[EMAX];               // sigmoid edge weights

// ---------------------------------------------------------------------------
// Kernel 1: per-node dot products with the two halves of w_pred; init deg=1.
// ---------------------------------------------------------------------------
__global__ void k_precompute(const float* __restrict__ x,
                             const float* __restrict__ wp, int n) {
    int warp = (blockIdx.x * blockDim.x + threadIdx.x) >> 5;
    int lane = threadIdx.x & 31;
    if (warp >= n) return;
    float4 xv = ((const float4*)(x + (size_t)warp * D))[lane];
    float4 w1 = ((const float4*)wp)[lane];
    float4 w2 = ((const float4*)(wp + D))[lane];
    float s1 = xv.x * w1.x + xv.y * w1.y + xv.z * w1.z + xv.w * w1.w;
    float s2 = xv.x * w2.x + xv.y * w2.y + xv.z * w2.z + xv.w * w2.w;
#pragma unroll
    for (int o = 16; o > 0; o >>= 1) {
        s1 += __shfl_xor_sync(0xffffffffu, s1, o);
        s2 += __shfl_xor_sync(0xffffffffu, s2, o);
    }
    if (lane == 0) {
        g_p1[warp] = s1;
        g_p2[warp] = s2;
        g_deg[warp] = 1.0f;
    }
}

// ---------------------------------------------------------------------------
// Kernel 2: edge weights (sigmoid) + weighted in-degree via atomics.
// ---------------------------------------------------------------------------
__global__ void k_edge(const int* __restrict__ src, const int* __restrict__ tgt,
                       const float* __restrict__ bp, int e) {
    int i = blockIdx.x * blockDim.x + threadIdx.x;
    if (i >= e) return;
    int s = src[i], t = tgt[i];
    float z = g_p1[s] + g_p2[t] + bp[0];
    float w = __fdividef(1.0f, 1.0f + __expf(-z));
    g_ew[i] = w;
    atomicAdd(&g_deg[t], w);
}

// ---------------------------------------------------------------------------
// Kernel 3: xw = x @ W. W (64KB) + 64-row X tile (32KB) in dynamic smem.
// 256 threads, each computes 8 rows x 4 cols.
// ---------------------------------------------------------------------------
__global__ void k_gemm(const float* __restrict__ x, const float* __restrict__ W,
                       int n) {
    extern __shared__ float sh[];
    float* Ws = sh;            // [k][j]  128*128
    float* Xs = sh + D * D;    // [r][k]  BM*128
    int tid = threadIdx.x;
    int row0 = blockIdx.x * BM;

    for (int i = tid; i < D * D / 4; i += 256)
        ((float4*)Ws)[i] = ((const float4*)W)[i];
    for (int i = tid; i < BM * D / 4; i += 256) {
        int r = i >> 5;
        int gr = row0 + r;
        float4 v = make_float4(0.f, 0.f, 0.f, 0.f);
        if (gr < n) v = ((const float4*)x)[(size_t)gr * 32 + (i & 31)];
        ((float4*)Xs)[i] = v;
    }
    __syncthreads();

    int tcol = tid & 31;
    int trow = tid >> 5;
    float acc[8][4];
#pragma unroll
    for (int i = 0; i < 8; i++)
#pragma unroll
        for (int j = 0; j < 4; j++) acc[i][j] = 0.f;

#pragma unroll 4
    for (int k = 0; k < D; k++) {
        float4 bv = *((const float4*)&Ws[k * D + tcol * 4]);
        float av[8];
#pragma unroll
        for (int i = 0; i < 8; i++) av[i] = Xs[(trow * 8 + i) * D + k];
#pragma unroll
        for (int i = 0; i < 8; i++) {
            acc[i][0] += av[i] * bv.x;
            acc[i][1] += av[i] * bv.y;
            acc[i][2] += av[i] * bv.z;
            acc[i][3] += av[i] * bv.w;
        }
    }

#pragma unroll
    for (int i = 0; i < 8; i++) {
        int gr = row0 + trow * 8 + i;
        if (gr < n)
            *((float4*)&g_xw[(size_t)gr * D + tcol * 4]) =
                make_float4(acc[i][0], acc[i][1], acc[i][2], acc[i][3]);
    }
}

// ---------------------------------------------------------------------------
// Kernel 4: dis = rsqrt(deg); out = b + dis^2 * xw (self loop + bias; also
// initializes the poisoned output buffer).
// ---------------------------------------------------------------------------
__global__ void k_selfinit(const float* __restrict__ b, float* __restrict__ out,
                           int n) {
    int i = blockIdx.x * blockDim.x + threadIdx.x;
    if (i >= n * 32) return;
    int node = i >> 5;
    int c4 = i & 31;
    float dg = g_deg[node];
    float ds = (dg > 0.f) ? rsqrtf(dg) : 0.f;
    float sc = ds * ds;
    float4 xv = ((const float4*)g_xw)[i];
    float4 bv = ((const float4*)b)[c4];
    ((float4*)out)[i] = make_float4(bv.x + sc * xv.x, bv.y + sc * xv.y,
                                    bv.z + sc * xv.z, bv.w + sc * xv.w);
    if (c4 == 0) g_dis[node] = ds;
}

// ---------------------------------------------------------------------------
// Kernel 5: edge scatter. Warp per edge: gather xw[src] (L2-resident),
// scale, then ONE red.global.add.v4.f32 per lane (4x fewer REDG ops than
// scalar atomicAdd).
// ---------------------------------------------------------------------------
__global__ void k_scatter(const int* __restrict__ src, const int* __restrict__ tgt,
                          float* __restrict__ out, int e) {
    int w = (blockIdx.x * blockDim.x + threadIdx.x) >> 5;
    int lane = threadIdx.x & 31;
    if (w >= e) return;
    int s = src[w], t = tgt[w];
    float c = g_dis[s] * g_ew[w] * g_dis[t];
    float4 v = ((const float4*)g_xw)[(size_t)s * 32 + lane];
    float* o = out + (size_t)t * D + lane * 4;
    asm volatile("red.global.add.v4.f32 [%0], {%1, %2, %3, %4};"
                 :: "l"(o), "f"(c * v.x), "f"(c * v.y), "f"(c * v.z),
                    "f"(c * v.w)
                 : "memory");
}

// ---------------------------------------------------------------------------
extern "C" void kernel_launch(void* const* d_in, const int* in_sizes, int n_in,
                              void* d_out, int out_size) {
    const float* x  = (const float*)d_in[0];
    const int*   ei = (const int*)d_in[1];
    const float* W  = (const float*)d_in[2];
    const float* b  = (const float*)d_in[3];
    const float* wp = (const float*)d_in[4];
    const float* bp = (const float*)d_in[5];
    float* out = (float*)d_out;

    int n = in_sizes[0] / D;
    int e = in_sizes[1] / 2;
    const int* src = ei;
    const int* tgt = ei + e;

    int smem = (D * D + BM * D) * (int)sizeof(float);  // 96 KB
    cudaFuncSetAttribute(k_gemm, cudaFuncAttributeMaxDynamicSharedMemorySize, smem);

    k_precompute<<<(n + 7) / 8, 256>>>(x, wp, n);
    k_edge<<<(e + 255) / 256, 256>>>(src, tgt, bp, e);
    k_gemm<<<(n + BM - 1) / BM, 256, smem>>>(x, W, n);
    k_selfinit<<<(n * 32 + 255) / 256, 256>>>(b, out, n);
    k_scatter<<<(e * 32 + 255) / 256, 256>>>(src, tgt, out, e);
}